// round 2
// baseline (speedup 1.0000x reference)
#include <cuda_runtime.h>
#include <cuda_bf16.h>
#include <math.h>

#define DEV_INLINE __device__ __forceinline__

// ---------------- problem constants ----------------
#define B_    16
#define S_    2048
#define D_    512
#define H_    2048
#define L_    4
#define M_    64
#define NTOK  (B_ * S_)   // 32768

// ---------------- scratch (device globals; no allocs allowed) ----------------
__device__ float g_h  [NTOK * D_];
__device__ float g_a  [NTOK * D_];
__device__ float g_b  [NTOK * D_];
__device__ float g_c  [NTOK * D_];
__device__ float g_pq [NTOK * M_];
__device__ float g_pk [NTOK * M_];
__device__ float g_kv [B_ * M_ * D_];
__device__ float g_pks[B_ * M_];
__device__ float g_pkpart[B_ * 16 * M_];
__device__ float g_ff [NTOK * H_];          // 256 MB
__device__ float g_s0 [B_ * D_];
__device__ float g_s1 [B_ * D_];
__device__ float g_s2 [B_ * M_];
__device__ float g_s3 [B_ * D_];
__device__ float g_sff[B_ * H_];

// ---------------- packed f32x2 helpers (sm_103a FFMA2) ----------------
DEV_INLINE unsigned long long pack_dup(float a) {
    unsigned long long r;
    asm("mov.b64 %0, {%1, %2};" : "=l"(r) : "f"(a), "f"(a));
    return r;
}
DEV_INLINE void ffma2(unsigned long long& d, unsigned long long a, unsigned long long b) {
    asm("fma.rn.f32x2 %0, %1, %2, %0;" : "+l"(d) : "l"(a), "l"(b));
}
DEV_INLINE float2 unpack2(unsigned long long v) {
    float2 f;
    asm("mov.b64 {%0, %1}, %2;" : "=f"(f.x), "=f"(f.y) : "l"(v));
    return f;
}

enum { ACT_NONE = 0, ACT_ELU1 = 1, ACT_GELU = 2 };

// ---------------- generic tiled SGEMM: C = act(A@B + bias) (+ res) ----------------
// A: M x K row-major, B: K x N row-major, C: M x N row-major.
// K must be a multiple of BK; N a multiple of BN. M is bounds-checked.
template <int BM, int BN, int BK, int TM, int TN, int ACT, bool HAS_BIAS, bool ADD_RES>
__global__ void __launch_bounds__((BM / TM) * (BN / TN))
gemm_kernel(const float* __restrict__ A, const float* __restrict__ Bw,
            const float* __restrict__ bias, const float* __restrict__ res,
            float* __restrict__ C, int M, int N, int K)
{
    constexpr int THREADS = (BM / TM) * (BN / TN);
    __shared__ __align__(16) float As[BK][BM];
    __shared__ __align__(16) float Bs[BK][BN];

    const int bm  = blockIdx.y * BM;
    const int bn  = blockIdx.x * BN;
    const int tid = threadIdx.x;
    constexpr int TCOLS = BN / TN;
    const int tc = tid % TCOLS;
    const int tr = tid / TCOLS;

    unsigned long long acc[TM][TN / 2];
#pragma unroll
    for (int i = 0; i < TM; i++)
#pragma unroll
        for (int j = 0; j < TN / 2; j++) acc[i][j] = 0ull;

    constexpr int A_VECS = BM * BK / 4;
    constexpr int B_VECS = BK * BN / 4;

    for (int k0 = 0; k0 < K; k0 += BK) {
        for (int i = tid; i < A_VECS; i += THREADS) {
            int r  = i / (BK / 4);
            int kc = (i % (BK / 4)) * 4;
            int gr = bm + r;
            float4 v4 = make_float4(0.f, 0.f, 0.f, 0.f);
            if (gr < M) v4 = *reinterpret_cast<const float4*>(A + (size_t)gr * K + k0 + kc);
            As[kc + 0][r] = v4.x; As[kc + 1][r] = v4.y;
            As[kc + 2][r] = v4.z; As[kc + 3][r] = v4.w;
        }
        for (int i = tid; i < B_VECS; i += THREADS) {
            int r = i / (BN / 4);
            int c = (i % (BN / 4)) * 4;
            *reinterpret_cast<float4*>(&Bs[r][c]) =
                *reinterpret_cast<const float4*>(Bw + (size_t)(k0 + r) * N + bn + c);
        }
        __syncthreads();
#pragma unroll
        for (int kk = 0; kk < BK; kk++) {
            unsigned long long ar[TM], br[TN / 2];
#pragma unroll
            for (int i = 0; i < TM; i++) ar[i] = pack_dup(As[kk][tr * TM + i]);
#pragma unroll
            for (int j = 0; j < TN / 2; j++)
                br[j] = *reinterpret_cast<const unsigned long long*>(&Bs[kk][tc * TN + 2 * j]);
#pragma unroll
            for (int i = 0; i < TM; i++)
#pragma unroll
                for (int j = 0; j < TN / 2; j++) ffma2(acc[i][j], ar[i], br[j]);
        }
        __syncthreads();
    }

#pragma unroll
    for (int i = 0; i < TM; i++) {
        int gr = bm + tr * TM + i;
        if (gr >= M) continue;
#pragma unroll
        for (int j = 0; j < TN / 2; j++) {
            int gc = bn + tc * TN + 2 * j;
            float2 v = unpack2(acc[i][j]);
            if (HAS_BIAS) { v.x += bias[gc]; v.y += bias[gc + 1]; }
            if (ACT == ACT_ELU1) {
                v.x = (v.x > 0.f) ? v.x + 1.f : expf(v.x);
                v.y = (v.y > 0.f) ? v.y + 1.f : expf(v.y);
            } else if (ACT == ACT_GELU) {
                v.x = 0.5f * v.x * (1.f + erff(v.x * 0.70710678118654752f));
                v.y = 0.5f * v.y * (1.f + erff(v.y * 0.70710678118654752f));
            }
            if (ADD_RES) {
                float2 rv = *reinterpret_cast<const float2*>(res + (size_t)gr * N + gc);
                v.x += rv.x; v.y += rv.y;
            }
            *reinterpret_cast<float2*>(C + (size_t)gr * N + gc) = v;
        }
    }
}

// ---------------- embedding: h[b,s,:] = embed[x[b,s],:] + pos[s,:] ----------------
__global__ void embed_kernel(const int* __restrict__ x, const float* __restrict__ emb,
                             const float* __restrict__ pos, float* __restrict__ h)
{
    int row = blockIdx.x;            // b*S + s
    int s   = row & (S_ - 1);
    int tok = __ldg(x + row);
    int c   = threadIdx.x * 4;       // 128 threads * 4 = 512
    float4 e = *reinterpret_cast<const float4*>(emb + (size_t)tok * D_ + c);
    float4 p = *reinterpret_cast<const float4*>(pos + (size_t)s * D_ + c);
    *reinterpret_cast<float4*>(h + (size_t)row * D_ + c) =
        make_float4(e.x + p.x, e.y + p.y, e.z + p.z, e.w + p.w);
}

// ---------------- kv[b,m,d] = sum_s pk[b,s,m] * v[b,s,d] ----------------
__global__ void kv_kernel(const float* __restrict__ pk, const float* __restrict__ v,
                          float* __restrict__ kv)
{
    const int b  = blockIdx.y;
    const int d0 = blockIdx.x * 64;
    __shared__ __align__(16) float spk[16][64];
    __shared__ __align__(16) float sv [16][64];
    const int tid = threadIdx.x;         // 256
    const int tx  = tid & 15;            // d group
    const int ty  = tid >> 4;            // m group
    float acc[4][4] = {};
    const float* pkb = pk + (size_t)b * S_ * M_;
    const float* vb  = v  + (size_t)b * S_ * D_ + d0;
    for (int s0 = 0; s0 < S_; s0 += 16) {
        int r  = tid >> 4;
        int c4 = (tid & 15) * 4;
        *reinterpret_cast<float4*>(&spk[r][c4]) =
            *reinterpret_cast<const float4*>(pkb + (size_t)(s0 + r) * M_ + c4);
        *reinterpret_cast<float4*>(&sv[r][c4]) =
            *reinterpret_cast<const float4*>(vb + (size_t)(s0 + r) * D_ + c4);
        __syncthreads();
#pragma unroll
        for (int kk = 0; kk < 16; kk++) {
            float4 am = *reinterpret_cast<float4*>(&spk[kk][ty * 4]);
            float4 bd = *reinterpret_cast<float4*>(&sv[kk][tx * 4]);
            float a[4] = {am.x, am.y, am.z, am.w};
            float d[4] = {bd.x, bd.y, bd.z, bd.w};
#pragma unroll
            for (int i = 0; i < 4; i++)
#pragma unroll
                for (int j = 0; j < 4; j++) acc[i][j] = fmaf(a[i], d[j], acc[i][j]);
        }
        __syncthreads();
    }
#pragma unroll
    for (int i = 0; i < 4; i++)
#pragma unroll
        for (int j = 0; j < 4; j++)
            kv[(size_t)b * M_ * D_ + (size_t)(ty * 4 + i) * D_ + d0 + tx * 4 + j] = acc[i][j];
}

// ---------------- pk column sums (deterministic two-stage) ----------------
__global__ void pksum_part(const float* __restrict__ pk, float* __restrict__ part)
{
    int b = blockIdx.y, ch = blockIdx.x, m = threadIdx.x;   // 64 threads
    const float* p = pk + ((size_t)b * S_ + (size_t)ch * 128) * M_ + m;
    float s = 0.f;
#pragma unroll 8
    for (int i = 0; i < 128; i++) s += p[(size_t)i * M_];
    part[(b * 16 + ch) * M_ + m] = s;
}
__global__ void pksum_red(const float* __restrict__ part, float* __restrict__ pks)
{
    int b = blockIdx.x, m = threadIdx.x;
    float s = 0.f;
#pragma unroll
    for (int c = 0; c < 16; c++) s += part[(b * 16 + c) * M_ + m];
    pks[b * M_ + m] = s;
}

// ---------------- att[b,r,d] = (pq[b,r,:] @ kv[b]) / (pq[b,r,:].pksum[b] + 1e-6) ----------------
template <int RB>
__global__ void att_kernel(const float* __restrict__ pq, const float* __restrict__ kvm,
                           const float* __restrict__ pksum, float* __restrict__ att,
                           int rows_per_batch)
{
    const int b  = blockIdx.y;
    const int r0 = blockIdx.x * RB;
    __shared__ float spq[RB][M_];
    __shared__ float spks[M_];
    __shared__ float sz[RB];
    const int tid = threadIdx.x;  // 256
    for (int i = tid; i < RB * M_; i += 256)
        spq[i >> 6][i & 63] = pq[((size_t)b * rows_per_batch + r0) * M_ + i];
    if (tid < M_) spks[tid] = pksum[b * M_ + tid];
    __syncthreads();
    if (tid < RB) {
        float z = 1e-6f;
#pragma unroll
        for (int m = 0; m < M_; m++) z = fmaf(spq[tid][m], spks[m], z);
        sz[tid] = z;
    }
    __syncthreads();
    const int d = 2 * tid;
    const float* kvb = kvm + (size_t)b * M_ * D_ + d;
    float2 acc[RB];
#pragma unroll
    for (int r = 0; r < RB; r++) acc[r] = make_float2(0.f, 0.f);
    for (int m = 0; m < M_; m++) {
        float2 kvv = *reinterpret_cast<const float2*>(kvb + (size_t)m * D_);
#pragma unroll
        for (int r = 0; r < RB; r++) {
            float a = spq[r][m];
            acc[r].x = fmaf(a, kvv.x, acc[r].x);
            acc[r].y = fmaf(a, kvv.y, acc[r].y);
        }
    }
#pragma unroll
    for (int r = 0; r < RB; r++) {
        float inv = 1.0f / sz[r];
        *reinterpret_cast<float2*>(att + ((size_t)b * rows_per_batch + r0 + r) * D_ + d) =
            make_float2(acc[r].x * inv, acc[r].y * inv);
    }
}

// ---------------- LayerNorm over last dim (512), 128 threads/row ----------------
__global__ void ln_kernel(const float* __restrict__ in, const float* __restrict__ g,
                          const float* __restrict__ bet, float* __restrict__ out)
{
    const int row = blockIdx.x;
    const int tid = threadIdx.x;  // 128
    float4 v = *reinterpret_cast<const float4*>(in + (size_t)row * D_ + tid * 4);
    __shared__ float red[4];
    float s = v.x + v.y + v.z + v.w;
#pragma unroll
    for (int o = 16; o; o >>= 1) s += __shfl_xor_sync(0xffffffffu, s, o);
    if ((tid & 31) == 0) red[tid >> 5] = s;
    __syncthreads();
    float mu = (red[0] + red[1] + red[2] + red[3]) * (1.f / 512.f);
    float dx = v.x - mu, dy = v.y - mu, dz = v.z - mu, dw = v.w - mu;
    float ss = dx * dx + dy * dy + dz * dz + dw * dw;
#pragma unroll
    for (int o = 16; o; o >>= 1) ss += __shfl_xor_sync(0xffffffffu, ss, o);
    __syncthreads();
    if ((tid & 31) == 0) red[tid >> 5] = ss;
    __syncthreads();
    float var  = (red[0] + red[1] + red[2] + red[3]) * (1.f / 512.f);
    float rstd = rsqrtf(var + 1e-5f);
    float4 gg = *reinterpret_cast<const float4*>(g + tid * 4);
    float4 bb = *reinterpret_cast<const float4*>(bet + tid * 4);
    *reinterpret_cast<float4*>(out + (size_t)row * D_ + tid * 4) =
        make_float4(dx * rstd * gg.x + bb.x, dy * rstd * gg.y + bb.y,
                    dz * rstd * gg.z + bb.z, dw * rstd * gg.w + bb.w);
}

// ---------------- gather h[:,0,:] ----------------
__global__ void gather0_kernel(const float* __restrict__ h, float* __restrict__ h0)
{
    int b = blockIdx.x;
    int c = threadIdx.x * 4;
    *reinterpret_cast<float4*>(h0 + (size_t)b * D_ + c) =
        *reinterpret_cast<const float4*>(h + (size_t)b * S_ * D_ + c);
}

// ---------------- classifier: out = relu(pooled@Wc1+bc1)@Wc2 + bc2 ----------------
__global__ void cls_kernel(const float* __restrict__ pooled, const float* __restrict__ Wc1,
                           const float* __restrict__ bc1, const float* __restrict__ Wc2,
                           const float* __restrict__ bc2, float* __restrict__ out)
{
    int b = blockIdx.x;
    int j = threadIdx.x;  // 256
    __shared__ float sp[D_];
    sp[j]       = pooled[(size_t)b * D_ + j];
    sp[j + 256] = pooled[(size_t)b * D_ + j + 256];
    __syncthreads();
    float acc = bc1[j];
    for (int d = 0; d < D_; d++) acc = fmaf(sp[d], Wc1[(size_t)d * 256 + j], acc);
    float hid = acc > 0.f ? acc : 0.f;
    float p0 = hid * Wc2[j * 2 + 0];
    float p1 = hid * Wc2[j * 2 + 1];
#pragma unroll
    for (int o = 16; o; o >>= 1) {
        p0 += __shfl_xor_sync(0xffffffffu, p0, o);
        p1 += __shfl_xor_sync(0xffffffffu, p1, o);
    }
    __shared__ float r0[8], r1[8];
    if ((j & 31) == 0) { r0[j >> 5] = p0; r1[j >> 5] = p1; }
    __syncthreads();
    if (j == 0) {
        float a0 = 0.f, a1 = 0.f;
#pragma unroll
        for (int w = 0; w < 8; w++) { a0 += r0[w]; a1 += r1[w]; }
        out[b * 2 + 0] = a0 + bc2[0];
        out[b * 2 + 1] = a1 + bc2[1];
    }
}

// ---------------- host launchers ----------------
template <int ACT, bool HB, bool AR>
static void gemm128(const float* A, const float* Bw, const float* bias, const float* res,
                    float* C, int M, int N, int K)
{
    dim3 grid(N / 128, (M + 127) / 128);
    gemm_kernel<128, 128, 16, 8, 8, ACT, HB, AR><<<grid, 256>>>(A, Bw, bias, res, C, M, N, K);
}
template <int ACT>
static void gemm64n(const float* A, const float* Bw, float* C, int M, int K)
{
    dim3 grid(1, (M + 127) / 128);
    gemm_kernel<128, 64, 16, 8, 8, ACT, false, false><<<grid, 128>>>(A, Bw, nullptr, nullptr, C, M, 64, K);
}

extern "C" void kernel_launch(void* const* d_in, const int* in_sizes, int n_in,
                              void* d_out, int out_size)
{
    const int*   x   = (const int*)  d_in[0];
    const float* emb = (const float*)d_in[1];
    const float* pos = (const float*)d_in[2];
    const float* Wq  = (const float*)d_in[3];
    const float* bq  = (const float*)d_in[4];
    const float* Wk  = (const float*)d_in[5];
    const float* bk  = (const float*)d_in[6];
    const float* Wv  = (const float*)d_in[7];
    const float* bv  = (const float*)d_in[8];
    const float* P   = (const float*)d_in[9];
    const float* Wo  = (const float*)d_in[10];
    const float* bo  = (const float*)d_in[11];
    const float* lng = (const float*)d_in[12];
    const float* lnb = (const float*)d_in[13];
    const float* W1  = (const float*)d_in[14];
    const float* b1  = (const float*)d_in[15];
    const float* W2  = (const float*)d_in[16];
    const float* b2  = (const float*)d_in[17];
    const float* Wc1 = (const float*)d_in[18];
    const float* bc1 = (const float*)d_in[19];
    const float* Wc2 = (const float*)d_in[20];
    const float* bc2 = (const float*)d_in[21];
    float* out = (float*)d_out;

    float *h_, *a_, *b_, *c_, *pq_, *pk_, *kv_, *pks_, *pkp_, *ff_, *s0_, *s1_, *s2_, *s3_, *sff_;
    cudaGetSymbolAddress((void**)&h_,  g_h);
    cudaGetSymbolAddress((void**)&a_,  g_a);
    cudaGetSymbolAddress((void**)&b_,  g_b);
    cudaGetSymbolAddress((void**)&c_,  g_c);
    cudaGetSymbolAddress((void**)&pq_, g_pq);
    cudaGetSymbolAddress((void**)&pk_, g_pk);
    cudaGetSymbolAddress((void**)&kv_, g_kv);
    cudaGetSymbolAddress((void**)&pks_, g_pks);
    cudaGetSymbolAddress((void**)&pkp_, g_pkpart);
    cudaGetSymbolAddress((void**)&ff_, g_ff);
    cudaGetSymbolAddress((void**)&s0_, g_s0);
    cudaGetSymbolAddress((void**)&s1_, g_s1);
    cudaGetSymbolAddress((void**)&s2_, g_s2);
    cudaGetSymbolAddress((void**)&s3_, g_s3);
    cudaGetSymbolAddress((void**)&sff_, g_sff);

    // h = embed[x] + pos
    embed_kernel<<<NTOK, 128>>>(x, emb, pos, h_);

    // full layers 0..2
    for (int l = 0; l < 3; l++) {
        const float* Wql = Wq + (size_t)l * D_ * D_;
        const float* Wkl = Wk + (size_t)l * D_ * D_;
        const float* Wvl = Wv + (size_t)l * D_ * D_;
        const float* Pl  = P  + (size_t)l * D_ * M_;
        const float* Wol = Wo + (size_t)l * D_ * D_;
        const float* W1l = W1 + (size_t)l * D_ * H_;
        const float* W2l = W2 + (size_t)l * H_ * D_;

        gemm128<ACT_NONE, true, false>(h_, Wql, bq + l * D_, nullptr, a_, NTOK, D_, D_);
        gemm128<ACT_NONE, true, false>(h_, Wkl, bk + l * D_, nullptr, b_, NTOK, D_, D_);
        gemm128<ACT_NONE, true, false>(h_, Wvl, bv + l * D_, nullptr, c_, NTOK, D_, D_);
        gemm64n<ACT_ELU1>(a_, Pl, pq_, NTOK, D_);
        gemm64n<ACT_ELU1>(b_, Pl, pk_, NTOK, D_);
        kv_kernel<<<dim3(D_ / 64, B_), 256>>>(pk_, c_, kv_);
        pksum_part<<<dim3(16, B_), 64>>>(pk_, pkp_);
        pksum_red<<<B_, 64>>>(pkp_, pks_);
        att_kernel<8><<<dim3(S_ / 8, B_), 256>>>(pq_, kv_, pks_, a_, S_);
        gemm128<ACT_NONE, true, false>(a_, Wol, bo + l * D_, nullptr, b_, NTOK, D_, D_);
        ln_kernel<<<NTOK, 128>>>(b_, lng + l * D_, lnb + l * D_, a_);
        gemm128<ACT_GELU, true, false>(a_, W1l, b1 + l * H_, nullptr, ff_, NTOK, H_, D_);
        gemm128<ACT_NONE, true, true >(ff_, W2l, b2 + l * D_, h_, h_, NTOK, D_, H_);
    }

    // layer 3: only position 0 survives to the classifier
    {
        const int l = 3;
        const float* Wql = Wq + (size_t)l * D_ * D_;
        const float* Wkl = Wk + (size_t)l * D_ * D_;
        const float* Wvl = Wv + (size_t)l * D_ * D_;
        const float* Pl  = P  + (size_t)l * D_ * M_;
        const float* Wol = Wo + (size_t)l * D_ * D_;
        const float* W1l = W1 + (size_t)l * D_ * H_;
        const float* W2l = W2 + (size_t)l * H_ * D_;

        gather0_kernel<<<B_, 128>>>(h_, s0_);                      // r = h[:,0,:]
        gemm128<ACT_NONE, true, false>(h_, Wkl, bk + l * D_, nullptr, b_, NTOK, D_, D_);
        gemm128<ACT_NONE, true, false>(h_, Wvl, bv + l * D_, nullptr, c_, NTOK, D_, D_);
        gemm64n<ACT_ELU1>(b_, Pl, pk_, NTOK, D_);
        kv_kernel<<<dim3(D_ / 64, B_), 256>>>(pk_, c_, kv_);
        pksum_part<<<dim3(16, B_), 64>>>(pk_, pkp_);
        pksum_red<<<B_, 64>>>(pkp_, pks_);

        gemm128<ACT_NONE, true, false>(s0_, Wql, bq + l * D_, nullptr, s1_, B_, D_, D_);
        gemm64n<ACT_ELU1>(s1_, Pl, s2_, B_, D_);
        att_kernel<1><<<dim3(1, B_), 256>>>(s2_, kv_, pks_, s3_, 1);
        gemm128<ACT_NONE, true, false>(s3_, Wol, bo + l * D_, nullptr, s1_, B_, D_, D_);
        ln_kernel<<<B_, 128>>>(s1_, lng + l * D_, lnb + l * D_, s3_);
        gemm128<ACT_GELU, true, false>(s3_, W1l, b1 + l * H_, nullptr, sff_, B_, H_, D_);
        gemm128<ACT_NONE, true, true >(sff_, W2l, b2 + l * D_, s0_, s1_, B_, D_, H_);
    }

    // classifier
    cls_kernel<<<B_, 256>>>(s1_, Wc1, bc1, Wc2, bc2, out);
}

// round 4
// speedup vs baseline: 2.5577x; 2.5577x over previous
#include <cuda_runtime.h>
#include <cuda_bf16.h>
#include <math.h>
#include <stdint.h>

#define DEV_INLINE __device__ __forceinline__

#define B_    16
#define S_    2048
#define D_    512
#define H_    2048
#define L_    4
#define M_    64
#define NTOK  (B_ * S_)

typedef __nv_bfloat16  bf16;
typedef __nv_bfloat162 bf162;

// ---------------- scratch ----------------
__device__ float g_h  [NTOK * D_];
__device__ float g_a  [NTOK * D_];
__device__ float g_b  [NTOK * D_];
__device__ float g_c  [NTOK * D_];
__device__ float g_pq [NTOK * M_];
__device__ float g_pk [NTOK * M_];
__device__ float g_kv [B_ * M_ * D_];
__device__ float g_pks[B_ * M_];
__device__ float g_pkpart[B_ * 16 * M_];
__device__ float g_ff [NTOK * H_];
__device__ float g_s0 [B_ * D_];
__device__ float g_s1 [B_ * D_];
__device__ float g_s2 [B_ * M_];
__device__ float g_s3 [B_ * D_];
__device__ float g_sff[B_ * H_];
// split+transposed weights: [N,K] bf16, hi & lo
__device__ bf16 g_Wqh[L_*D_*D_], g_Wqlo[L_*D_*D_];
__device__ bf16 g_Wkh[L_*D_*D_], g_Wklo[L_*D_*D_];
__device__ bf16 g_Wvh[L_*D_*D_], g_Wvlo[L_*D_*D_];
__device__ bf16 g_Woh[L_*D_*D_], g_Wolo[L_*D_*D_];
__device__ bf16 g_Ph [L_*M_*D_], g_Plo [L_*M_*D_];
__device__ bf16 g_W1h[L_*H_*D_], g_W1lo[L_*H_*D_];
__device__ bf16 g_W2h[L_*D_*H_], g_W2lo[L_*D_*H_];

// ---------------- helpers ----------------
DEV_INLINE uint32_t smem_u32(const void* p) {
    uint32_t a;
    asm("{ .reg .u64 t; cvta.to.shared.u64 t, %1; cvt.u32.u64 %0, t; }" : "=r"(a) : "l"(p));
    return a;
}
DEV_INLINE void cp16(uint32_t dst, const void* src) {
    asm volatile("cp.async.cg.shared.global [%0], [%1], 16;"
                 :: "r"(dst), "l"(__cvta_generic_to_global(src)));
}
DEV_INLINE void cp_commit() { asm volatile("cp.async.commit_group;"); }
template<int N> DEV_INLINE void cp_wait() {
    asm volatile("cp.async.wait_group %0;" :: "n"(N) : "memory");
}
DEV_INLINE void ldm_x4(uint32_t& r0, uint32_t& r1, uint32_t& r2, uint32_t& r3, uint32_t addr) {
    asm volatile("ldmatrix.sync.aligned.m8n8.x4.shared.b16 {%0,%1,%2,%3}, [%4];"
                 : "=r"(r0), "=r"(r1), "=r"(r2), "=r"(r3) : "r"(addr));
}
DEV_INLINE void mma16816(float* d, const uint32_t* a, const uint32_t* b) {
    asm volatile("mma.sync.aligned.m16n8k16.row.col.f32.bf16.bf16.f32 "
                 "{%0,%1,%2,%3}, {%4,%5,%6,%7}, {%8,%9}, {%0,%1,%2,%3};"
                 : "+f"(d[0]), "+f"(d[1]), "+f"(d[2]), "+f"(d[3])
                 : "r"(a[0]), "r"(a[1]), "r"(a[2]), "r"(a[3]), "r"(b[0]), "r"(b[1]));
}
DEV_INLINE void split_bf16(float v, bf16& h, bf16& l) {
    h = __float2bfloat16(v);
    l = __float2bfloat16(v - __bfloat162float(h));
}
DEV_INLINE uint32_t pk2(bf16 a, bf16 b) {
    bf162 t; t.x = a; t.y = b; return *reinterpret_cast<uint32_t*>(&t);
}

enum { ACT_NONE = 0, ACT_ELU1 = 1, ACT_GELU = 2 };

// ================= split-bf16 HMMA GEMM =================
// C[M,N] = act(A@B^T + bias)(+res). A:[M,K] fp32 (split hi/lo on the fly).
// Bh/Bl:[N,K] bf16 K-major. M%128==0, N%BN==0, K%64==0.
template<int BN, int ACT, bool HAS_BIAS, bool ADD_RES>
__global__ void __launch_bounds__(256)
mma_gemm_kernel(const float* __restrict__ A, const bf16* __restrict__ Bh,
                const bf16* __restrict__ Bl, const float* __restrict__ bias,
                const float* __restrict__ res, float* __restrict__ C,
                int M, int N, int K)
{
    constexpr int SA   = 72;                       // padded row stride (elems)
    constexpr int ABYT = 128 * SA * 2;             // one A matrix (hi or lo)
    constexpr int BBYT = BN * SA * 2;              // one B matrix
    constexpr int STAGE = 2 * ABYT + 2 * BBYT;
    constexpr int WN = BN / 4;                     // warp tile N (32 or 16)
    constexpr int NT = WN / 8;                     // n8 tiles per warp (4 or 2)
    constexpr int NG = WN / 16;                    // ldmatrix-x4 groups (2 or 1)

    extern __shared__ __align__(16) char smem[];
    const int tid  = threadIdx.x;
    const int wid  = tid >> 5;
    const int lane = tid & 31;
    const int bm   = blockIdx.y * 128;
    const int bn   = blockIdx.x * BN;
    const int wm   = (wid >> 2) * 64;
    const int wn   = (wid & 3) * WN;

    float acc[4][NT][4];
#pragma unroll
    for (int i = 0; i < 4; i++)
#pragma unroll
        for (int j = 0; j < NT; j++)
#pragma unroll
            for (int q = 0; q < 4; q++) acc[i][j][q] = 0.f;

    float4 aregs[8];
    auto ldA = [&](int c) {
        const size_t ko = (size_t)c * 64;
#pragma unroll
        for (int i = 0; i < 8; i++) {
            int idx = tid + i * 256;
            int r = idx >> 4, c4 = (idx & 15) * 4;
            aregs[i] = *reinterpret_cast<const float4*>(A + (size_t)(bm + r) * K + ko + c4);
        }
    };
    auto stA = [&](char* st) {
#pragma unroll
        for (int i = 0; i < 8; i++) {
            int idx = tid + i * 256;
            int r = idx >> 4, c4 = (idx & 15) * 4;
            float4 v = aregs[i];
            bf16 h0,l0,h1,l1,h2,l2,h3,l3;
            split_bf16(v.x,h0,l0); split_bf16(v.y,h1,l1);
            split_bf16(v.z,h2,l2); split_bf16(v.w,h3,l3);
            uint32_t off = (uint32_t)(r * SA + c4) * 2;
            *reinterpret_cast<uint2*>(st + off)        = make_uint2(pk2(h0,h1), pk2(h2,h3));
            *reinterpret_cast<uint2*>(st + ABYT + off) = make_uint2(pk2(l0,l1), pk2(l2,l3));
        }
    };
    auto ldB = [&](int c, char* st) {
        const size_t ko = (size_t)c * 64;
        const uint32_t bbase = smem_u32(st) + 2 * ABYT;
#pragma unroll
        for (int i = 0; i < BN * 8 / 256; i++) {
            int idx = tid + i * 256;
            int r = idx >> 3, cs = idx & 7;
            uint32_t dst = bbase + (uint32_t)(r * SA + cs * 8) * 2;
            cp16(dst,        Bh + (size_t)(bn + r) * K + ko + cs * 8);
            cp16(dst + BBYT, Bl + (size_t)(bn + r) * K + ko + cs * 8);
        }
        cp_commit();
    };

    const int C_ = K >> 6;
    ldA(0);
    ldB(0, smem);
    stA(smem);
    cp_wait<0>();
    __syncthreads();

    for (int c = 0; c < C_; c++) {
        char* cur = smem + (size_t)(c & 1) * STAGE;
        char* nxt = smem + (size_t)((c & 1) ^ 1) * STAGE;
        if (c + 1 < C_) { ldA(c + 1); ldB(c + 1, nxt); }

        const uint32_t ah_base = smem_u32(cur);
        const uint32_t al_base = ah_base + ABYT;
        const uint32_t bh_base = ah_base + 2 * ABYT;
        const uint32_t bl_base = bh_base + BBYT;
        const int arow = (lane & 15);
        const int acol8 = (lane >> 4) * 8;
        const int brow = (lane & 7) + ((lane >> 4) & 1) * 8;
        const int bcol8 = ((lane >> 3) & 1) * 8;

#pragma unroll
        for (int kk = 0; kk < 4; kk++) {
            uint32_t ah[4][4], al[4][4];
#pragma unroll
            for (int mi = 0; mi < 4; mi++) {
                uint32_t off = (uint32_t)((wm + mi * 16 + arow) * SA + kk * 16 + acol8) * 2;
                ldm_x4(ah[mi][0], ah[mi][1], ah[mi][2], ah[mi][3], ah_base + off);
                ldm_x4(al[mi][0], al[mi][1], al[mi][2], al[mi][3], al_base + off);
            }
            uint32_t bh[NT][2], bl[NT][2];
#pragma unroll
            for (int g = 0; g < NG; g++) {
                uint32_t off = (uint32_t)((wn + g * 16 + brow) * SA + kk * 16 + bcol8) * 2;
                uint32_t r0, r1, r2, r3;
                ldm_x4(r0, r1, r2, r3, bh_base + off);
                bh[2*g][0] = r0; bh[2*g][1] = r1; bh[2*g+1][0] = r2; bh[2*g+1][1] = r3;
                ldm_x4(r0, r1, r2, r3, bl_base + off);
                bl[2*g][0] = r0; bl[2*g][1] = r1; bl[2*g+1][0] = r2; bl[2*g+1][1] = r3;
            }
#pragma unroll
            for (int mi = 0; mi < 4; mi++)
#pragma unroll
                for (int nt = 0; nt < NT; nt++) {
                    mma16816(acc[mi][nt], ah[mi], bh[nt]);
                    mma16816(acc[mi][nt], ah[mi], bl[nt]);
                    mma16816(acc[mi][nt], al[mi], bh[nt]);
                }
        }

        if (c + 1 < C_) { stA(nxt); cp_wait<0>(); }
        __syncthreads();
    }

    // ---- epilogue ----
    const int rbase = bm + wm + (lane >> 2);
    const int cbase = bn + wn + (lane & 3) * 2;
#pragma unroll
    for (int mi = 0; mi < 4; mi++) {
#pragma unroll
        for (int nt = 0; nt < NT; nt++) {
            const int col = cbase + nt * 8;
            float bx = 0.f, by = 0.f;
            if (HAS_BIAS) { bx = __ldg(bias + col); by = __ldg(bias + col + 1); }
#pragma unroll
            for (int half = 0; half < 2; half++) {
                const int row = rbase + mi * 16 + half * 8;
                float vx = acc[mi][nt][half * 2 + 0] + bx;
                float vy = acc[mi][nt][half * 2 + 1] + by;
                if (ACT == ACT_ELU1) {
                    vx = (vx > 0.f) ? vx + 1.f : expf(vx);
                    vy = (vy > 0.f) ? vy + 1.f : expf(vy);
                } else if (ACT == ACT_GELU) {
                    vx = 0.5f * vx * (1.f + erff(vx * 0.70710678118654752f));
                    vy = 0.5f * vy * (1.f + erff(vy * 0.70710678118654752f));
                }
                const size_t ro = (size_t)row * N + col;
                if (ADD_RES) {
                    float2 rr = *reinterpret_cast<const float2*>(res + ro);
                    vx += rr.x; vy += rr.y;
                }
                *reinterpret_cast<float2*>(C + ro) = make_float2(vx, vy);
            }
        }
    }
}

template<int BN, int ACT, bool HB, bool AR>
static void tcg(const float* A, const bf16* Bh, const bf16* Bl, const float* bias,
                const float* res, float* C, int M, int N, int K)
{
    constexpr int STAGE = 2 * (128 * 72 * 2) + 2 * (BN * 72 * 2);
    size_t sm = 2 * (size_t)STAGE;
    auto k = mma_gemm_kernel<BN, ACT, HB, AR>;
    cudaFuncSetAttribute(k, cudaFuncAttributeMaxDynamicSharedMemorySize, (int)sm);
    k<<<dim3(N / BN, M / 128), 256, sm>>>(A, Bh, Bl, bias, res, C, M, N, K);
}

// ============ weight transpose+split: W[K,N] fp32 -> Wh/Wl[N,K] bf16 ============
__global__ void wsplit_kernel(const float* __restrict__ W, int K, int N,
                              bf16* __restrict__ Wh, bf16* __restrict__ Wl)
{
    __shared__ float tile[32][33];
    const int l = blockIdx.z;
    const float* Ws = W + (size_t)l * K * N;
    bf16* Whd = Wh + (size_t)l * N * K;
    bf16* Wld = Wl + (size_t)l * N * K;
    const int n0 = blockIdx.x * 32, k0 = blockIdx.y * 32;
    const int tx = threadIdx.x, ty = threadIdx.y;   // (32,8)
#pragma unroll
    for (int i = 0; i < 4; i++)
        tile[ty + i * 8][tx] = Ws[(size_t)(k0 + ty + i * 8) * N + n0 + tx];
    __syncthreads();
#pragma unroll
    for (int i = 0; i < 4; i++) {
        float v = tile[tx][ty + i * 8];
        bf16 h, lo; split_bf16(v, h, lo);
        size_t o = (size_t)(n0 + ty + i * 8) * K + k0 + tx;
        Whd[o] = h; Wld[o] = lo;
    }
}

// ================= fp32 FFMA2 SGEMM (small layer-3 path) =================
DEV_INLINE unsigned long long pack_dup(float a) {
    unsigned long long r;
    asm("mov.b64 %0, {%1, %2};" : "=l"(r) : "f"(a), "f"(a));
    return r;
}
DEV_INLINE void ffma2(unsigned long long& d, unsigned long long a, unsigned long long b) {
    asm("fma.rn.f32x2 %0, %1, %2, %0;" : "+l"(d) : "l"(a), "l"(b));
}
DEV_INLINE float2 unpack2(unsigned long long v) {
    float2 f;
    asm("mov.b64 {%0, %1}, %2;" : "=f"(f.x), "=f"(f.y) : "l"(v));
    return f;
}

template <int BM, int BN, int BK, int TM, int TN, int ACT, bool HAS_BIAS, bool ADD_RES>
__global__ void __launch_bounds__((BM / TM) * (BN / TN))
gemm_kernel(const float* __restrict__ A, const float* __restrict__ Bw,
            const float* __restrict__ bias, const float* __restrict__ res,
            float* __restrict__ C, int M, int N, int K)
{
    constexpr int THREADS = (BM / TM) * (BN / TN);
    __shared__ __align__(16) float As[BK][BM];
    __shared__ __align__(16) float Bs[BK][BN];
    const int bm = blockIdx.y * BM, bn = blockIdx.x * BN, tid = threadIdx.x;
    constexpr int TCOLS = BN / TN;
    const int tc = tid % TCOLS, tr = tid / TCOLS;
    unsigned long long acc[TM][TN / 2];
#pragma unroll
    for (int i = 0; i < TM; i++)
#pragma unroll
        for (int j = 0; j < TN / 2; j++) acc[i][j] = 0ull;
    for (int k0 = 0; k0 < K; k0 += BK) {
        for (int i = tid; i < BM * BK / 4; i += THREADS) {
            int r = i / (BK / 4), kc = (i % (BK / 4)) * 4, gr = bm + r;
            float4 v4 = make_float4(0.f, 0.f, 0.f, 0.f);
            if (gr < M) v4 = *reinterpret_cast<const float4*>(A + (size_t)gr * K + k0 + kc);
            As[kc][r] = v4.x; As[kc+1][r] = v4.y; As[kc+2][r] = v4.z; As[kc+3][r] = v4.w;
        }
        for (int i = tid; i < BK * BN / 4; i += THREADS) {
            int r = i / (BN / 4), c = (i % (BN / 4)) * 4;
            *reinterpret_cast<float4*>(&Bs[r][c]) =
                *reinterpret_cast<const float4*>(Bw + (size_t)(k0 + r) * N + bn + c);
        }
        __syncthreads();
#pragma unroll
        for (int kk = 0; kk < BK; kk++) {
            unsigned long long ar[TM], br[TN / 2];
#pragma unroll
            for (int i = 0; i < TM; i++) ar[i] = pack_dup(As[kk][tr * TM + i]);
#pragma unroll
            for (int j = 0; j < TN / 2; j++)
                br[j] = *reinterpret_cast<const unsigned long long*>(&Bs[kk][tc * TN + 2 * j]);
#pragma unroll
            for (int i = 0; i < TM; i++)
#pragma unroll
                for (int j = 0; j < TN / 2; j++) ffma2(acc[i][j], ar[i], br[j]);
        }
        __syncthreads();
    }
#pragma unroll
    for (int i = 0; i < TM; i++) {
        int gr = bm + tr * TM + i;
        if (gr >= M) continue;
#pragma unroll
        for (int j = 0; j < TN / 2; j++) {
            int gc = bn + tc * TN + 2 * j;
            float2 v = unpack2(acc[i][j]);
            if (HAS_BIAS) { v.x += bias[gc]; v.y += bias[gc + 1]; }
            if (ACT == ACT_ELU1) {
                v.x = (v.x > 0.f) ? v.x + 1.f : expf(v.x);
                v.y = (v.y > 0.f) ? v.y + 1.f : expf(v.y);
            } else if (ACT == ACT_GELU) {
                v.x = 0.5f * v.x * (1.f + erff(v.x * 0.70710678118654752f));
                v.y = 0.5f * v.y * (1.f + erff(v.y * 0.70710678118654752f));
            }
            if (ADD_RES) {
                float2 rv = *reinterpret_cast<const float2*>(res + (size_t)gr * N + gc);
                v.x += rv.x; v.y += rv.y;
            }
            *reinterpret_cast<float2*>(C + (size_t)gr * N + gc) = v;
        }
    }
}

template <int ACT, bool HB, bool AR>
static void gemm128(const float* A, const float* Bw, const float* bias, const float* res,
                    float* C, int M, int N, int K)
{
    dim3 grid(N / 128, (M + 127) / 128);
    gemm_kernel<128, 128, 16, 8, 8, ACT, HB, AR><<<grid, 256>>>(A, Bw, bias, res, C, M, N, K);
}
template <int ACT>
static void gemm64n(const float* A, const float* Bw, float* C, int M, int K)
{
    dim3 grid(1, (M + 127) / 128);
    gemm_kernel<128, 64, 16, 8, 8, ACT, false, false><<<grid, 128>>>(A, Bw, nullptr, nullptr, C, M, 64, K);
}

// ================= elementwise / reduction kernels =================
__global__ void embed_kernel(const int* __restrict__ x, const float* __restrict__ emb,
                             const float* __restrict__ pos, float* __restrict__ h)
{
    int row = blockIdx.x;
    int s   = row & (S_ - 1);
    int tok = __ldg(x + row);
    int c   = threadIdx.x * 4;
    float4 e = *reinterpret_cast<const float4*>(emb + (size_t)tok * D_ + c);
    float4 p = *reinterpret_cast<const float4*>(pos + (size_t)s * D_ + c);
    *reinterpret_cast<float4*>(h + (size_t)row * D_ + c) =
        make_float4(e.x + p.x, e.y + p.y, e.z + p.z, e.w + p.w);
}

__global__ void kv_kernel(const float* __restrict__ pk, const float* __restrict__ v,
                          float* __restrict__ kv)
{
    const int b  = blockIdx.y;
    const int d0 = blockIdx.x * 64;
    __shared__ __align__(16) float spk[16][64];
    __shared__ __align__(16) float sv [16][64];
    const int tid = threadIdx.x, tx = tid & 15, ty = tid >> 4;
    float acc[4][4] = {};
    const float* pkb = pk + (size_t)b * S_ * M_;
    const float* vb  = v  + (size_t)b * S_ * D_ + d0;
    for (int s0 = 0; s0 < S_; s0 += 16) {
        int r = tid >> 4, c4 = (tid & 15) * 4;
        *reinterpret_cast<float4*>(&spk[r][c4]) =
            *reinterpret_cast<const float4*>(pkb + (size_t)(s0 + r) * M_ + c4);
        *reinterpret_cast<float4*>(&sv[r][c4]) =
            *reinterpret_cast<const float4*>(vb + (size_t)(s0 + r) * D_ + c4);
        __syncthreads();
#pragma unroll
        for (int kk = 0; kk < 16; kk++) {
            float4 am = *reinterpret_cast<float4*>(&spk[kk][ty * 4]);
            float4 bd = *reinterpret_cast<float4*>(&sv[kk][tx * 4]);
            float a[4] = {am.x, am.y, am.z, am.w};
            float d[4] = {bd.x, bd.y, bd.z, bd.w};
#pragma unroll
            for (int i = 0; i < 4; i++)
#pragma unroll
                for (int j = 0; j < 4; j++) acc[i][j] = fmaf(a[i], d[j], acc[i][j]);
        }
        __syncthreads();
    }
#pragma unroll
    for (int i = 0; i < 4; i++)
#pragma unroll
        for (int j = 0; j < 4; j++)
            kv[(size_t)b * M_ * D_ + (size_t)(ty * 4 + i) * D_ + d0 + tx * 4 + j] = acc[i][j];
}

__global__ void pksum_part(const float* __restrict__ pk, float* __restrict__ part)
{
    int b = blockIdx.y, ch = blockIdx.x, m = threadIdx.x;
    const float* p = pk + ((size_t)b * S_ + (size_t)ch * 128) * M_ + m;
    float s = 0.f;
#pragma unroll 8
    for (int i = 0; i < 128; i++) s += p[(size_t)i * M_];
    part[(b * 16 + ch) * M_ + m] = s;
}
__global__ void pksum_red(const float* __restrict__ part, float* __restrict__ pks)
{
    int b = blockIdx.x, m = threadIdx.x;
    float s = 0.f;
#pragma unroll
    for (int c = 0; c < 16; c++) s += part[(b * 16 + c) * M_ + m];
    pks[b * M_ + m] = s;
}

template <int RB>
__global__ void att_kernel(const float* __restrict__ pq, const float* __restrict__ kvm,
                           const float* __restrict__ pksum, float* __restrict__ att,
                           int rows_per_batch)
{
    const int b  = blockIdx.y;
    const int r0 = blockIdx.x * RB;
    __shared__ float spq[RB][M_];
    __shared__ float spks[M_];
    __shared__ float sz[RB];
    const int tid = threadIdx.x;
    for (int i = tid; i < RB * M_; i += 256)
        spq[i >> 6][i & 63] = pq[((size_t)b * rows_per_batch + r0) * M_ + i];
    if (tid < M_) spks[tid] = pksum[b * M_ + tid];
    __syncthreads();
    if (tid < RB) {
        float z = 1e-6f;
#pragma unroll
        for (int m = 0; m < M_; m++) z = fmaf(spq[tid][m], spks[m], z);
        sz[tid] = z;
    }
    __syncthreads();
    const int d = 2 * tid;
    const float* kvb = kvm + (size_t)b * M_ * D_ + d;
    float2 acc[RB];
#pragma unroll
    for (int r = 0; r < RB; r++) acc[r] = make_float2(0.f, 0.f);
    for (int m = 0; m < M_; m++) {
        float2 kvv = *reinterpret_cast<const float2*>(kvb + (size_t)m * D_);
#pragma unroll
        for (int r = 0; r < RB; r++) {
            float a = spq[r][m];
            acc[r].x = fmaf(a, kvv.x, acc[r].x);
            acc[r].y = fmaf(a, kvv.y, acc[r].y);
        }
    }
#pragma unroll
    for (int r = 0; r < RB; r++) {
        float inv = 1.0f / sz[r];
        *reinterpret_cast<float2*>(att + ((size_t)b * rows_per_batch + r0 + r) * D_ + d) =
            make_float2(acc[r].x * inv, acc[r].y * inv);
    }
}

__global__ void ln_kernel(const float* __restrict__ in, const float* __restrict__ g,
                          const float* __restrict__ bet, float* __restrict__ out)
{
    const int row = blockIdx.x;
    const int tid = threadIdx.x;
    float4 v = *reinterpret_cast<const float4*>(in + (size_t)row * D_ + tid * 4);
    __shared__ float red[4];
    float s = v.x + v.y + v.z + v.w;
#pragma unroll
    for (int o = 16; o; o >>= 1) s += __shfl_xor_sync(0xffffffffu, s, o);
    if ((tid & 31) == 0) red[tid >> 5] = s;
    __syncthreads();
    float mu = (red[0] + red[1] + red[2] + red[3]) * (1.f / 512.f);
    float dx = v.x - mu, dy = v.y - mu, dz = v.z - mu, dw = v.w - mu;
    float ss = dx * dx + dy * dy + dz * dz + dw * dw;
#pragma unroll
    for (int o = 16; o; o >>= 1) ss += __shfl_xor_sync(0xffffffffu, ss, o);
    __syncthreads();
    if ((tid & 31) == 0) red[tid >> 5] = ss;
    __syncthreads();
    float var  = (red[0] + red[1] + red[2] + red[3]) * (1.f / 512.f);
    float rstd = rsqrtf(var + 1e-5f);
    float4 gg = *reinterpret_cast<const float4*>(g + tid * 4);
    float4 bb = *reinterpret_cast<const float4*>(bet + tid * 4);
    *reinterpret_cast<float4*>(out + (size_t)row * D_ + tid * 4) =
        make_float4(dx * rstd * gg.x + bb.x, dy * rstd * gg.y + bb.y,
                    dz * rstd * gg.z + bb.z, dw * rstd * gg.w + bb.w);
}

__global__ void gather0_kernel(const float* __restrict__ h, float* __restrict__ h0)
{
    int b = blockIdx.x;
    int c = threadIdx.x * 4;
    *reinterpret_cast<float4*>(h0 + (size_t)b * D_ + c) =
        *reinterpret_cast<const float4*>(h + (size_t)b * S_ * D_ + c);
}

__global__ void cls_kernel(const float* __restrict__ pooled, const float* __restrict__ Wc1,
                           const float* __restrict__ bc1, const float* __restrict__ Wc2,
                           const float* __restrict__ bc2, float* __restrict__ out)
{
    int b = blockIdx.x;
    int j = threadIdx.x;
    __shared__ float sp[D_];
    sp[j]       = pooled[(size_t)b * D_ + j];
    sp[j + 256] = pooled[(size_t)b * D_ + j + 256];
    __syncthreads();
    float acc = bc1[j];
    for (int d = 0; d < D_; d++) acc = fmaf(sp[d], Wc1[(size_t)d * 256 + j], acc);
    float hid = acc > 0.f ? acc : 0.f;
    float p0 = hid * Wc2[j * 2 + 0];
    float p1 = hid * Wc2[j * 2 + 1];
#pragma unroll
    for (int o = 16; o; o >>= 1) {
        p0 += __shfl_xor_sync(0xffffffffu, p0, o);
        p1 += __shfl_xor_sync(0xffffffffu, p1, o);
    }
    __shared__ float r0[8], r1[8];
    if ((j & 31) == 0) { r0[j >> 5] = p0; r1[j >> 5] = p1; }
    __syncthreads();
    if (j == 0) {
        float a0 = 0.f, a1 = 0.f;
#pragma unroll
        for (int w = 0; w < 8; w++) { a0 += r0[w]; a1 += r1[w]; }
        out[b * 2 + 0] = a0 + bc2[0];
        out[b * 2 + 1] = a1 + bc2[1];
    }
}

// ================= host =================
extern "C" void kernel_launch(void* const* d_in, const int* in_sizes, int n_in,
                              void* d_out, int out_size)
{
    const int*   x   = (const int*)  d_in[0];
    const float* emb = (const float*)d_in[1];
    const float* pos = (const float*)d_in[2];
    const float* Wq  = (const float*)d_in[3];
    const float* bq  = (const float*)d_in[4];
    const float* Wk  = (const float*)d_in[5];
    const float* bk  = (const float*)d_in[6];
    const float* Wv  = (const float*)d_in[7];
    const float* bv  = (const float*)d_in[8];
    const float* P   = (const float*)d_in[9];
    const float* Wo  = (const float*)d_in[10];
    const float* bo  = (const float*)d_in[11];
    const float* lng = (const float*)d_in[12];
    const float* lnb = (const float*)d_in[13];
    const float* W1  = (const float*)d_in[14];
    const float* b1  = (const float*)d_in[15];
    const float* W2  = (const float*)d_in[16];
    const float* b2  = (const float*)d_in[17];
    const float* Wc1 = (const float*)d_in[18];
    const float* bc1 = (const float*)d_in[19];
    const float* Wc2 = (const float*)d_in[20];
    const float* bc2 = (const float*)d_in[21];
    float* out = (float*)d_out;

    float *h_, *a_, *b_, *c_, *pq_, *pk_, *kv_, *pks_, *pkp_, *ff_, *s0_, *s1_, *s2_, *s3_, *sff_;
    bf16 *Wqh,*Wql_,*Wkh,*Wkl_,*Wvh,*Wvl_,*Woh,*Wol_,*Ph,*Pl_,*W1h,*W1l_,*W2h,*W2l_;
    cudaGetSymbolAddress((void**)&h_,  g_h);   cudaGetSymbolAddress((void**)&a_,  g_a);
    cudaGetSymbolAddress((void**)&b_,  g_b);   cudaGetSymbolAddress((void**)&c_,  g_c);
    cudaGetSymbolAddress((void**)&pq_, g_pq);  cudaGetSymbolAddress((void**)&pk_, g_pk);
    cudaGetSymbolAddress((void**)&kv_, g_kv);  cudaGetSymbolAddress((void**)&pks_, g_pks);
    cudaGetSymbolAddress((void**)&pkp_, g_pkpart); cudaGetSymbolAddress((void**)&ff_, g_ff);
    cudaGetSymbolAddress((void**)&s0_, g_s0);  cudaGetSymbolAddress((void**)&s1_, g_s1);
    cudaGetSymbolAddress((void**)&s2_, g_s2);  cudaGetSymbolAddress((void**)&s3_, g_s3);
    cudaGetSymbolAddress((void**)&sff_, g_sff);
    cudaGetSymbolAddress((void**)&Wqh, g_Wqh); cudaGetSymbolAddress((void**)&Wql_, g_Wqlo);
    cudaGetSymbolAddress((void**)&Wkh, g_Wkh); cudaGetSymbolAddress((void**)&Wkl_, g_Wklo);
    cudaGetSymbolAddress((void**)&Wvh, g_Wvh); cudaGetSymbolAddress((void**)&Wvl_, g_Wvlo);
    cudaGetSymbolAddress((void**)&Woh, g_Woh); cudaGetSymbolAddress((void**)&Wol_, g_Wolo);
    cudaGetSymbolAddress((void**)&Ph,  g_Ph);  cudaGetSymbolAddress((void**)&Pl_,  g_Plo);
    cudaGetSymbolAddress((void**)&W1h, g_W1h); cudaGetSymbolAddress((void**)&W1l_, g_W1lo);
    cudaGetSymbolAddress((void**)&W2h, g_W2h); cudaGetSymbolAddress((void**)&W2l_, g_W2lo);

    dim3 t328(32, 8);
    wsplit_kernel<<<dim3(16, 16, L_), t328>>>(Wq, D_, D_, Wqh, Wql_);
    wsplit_kernel<<<dim3(16, 16, L_), t328>>>(Wk, D_, D_, Wkh, Wkl_);
    wsplit_kernel<<<dim3(16, 16, L_), t328>>>(Wv, D_, D_, Wvh, Wvl_);
    wsplit_kernel<<<dim3(16, 16, L_), t328>>>(Wo, D_, D_, Woh, Wol_);
    wsplit_kernel<<<dim3(2,  16, L_), t328>>>(P,  D_, M_, Ph,  Pl_);
    wsplit_kernel<<<dim3(64, 16, L_), t328>>>(W1, D_, H_, W1h, W1l_);
    wsplit_kernel<<<dim3(16, 64, L_), t328>>>(W2, H_, D_, W2h, W2l_);

    embed_kernel<<<NTOK, 128>>>(x, emb, pos, h_);

    for (int l = 0; l < 3; l++) {
        const size_t dd = (size_t)l * D_ * D_, md = (size_t)l * M_ * D_;
        const size_t hd = (size_t)l * H_ * D_, dh = (size_t)l * D_ * H_;
        tcg<128, ACT_NONE, true, false>(h_, Wqh + dd, Wql_ + dd, bq + l * D_, nullptr, a_, NTOK, D_, D_);
        tcg<128, ACT_NONE, true, false>(h_, Wkh + dd, Wkl_ + dd, bk + l * D_, nullptr, b_, NTOK, D_, D_);
        tcg<128, ACT_NONE, true, false>(h_, Wvh + dd, Wvl_ + dd, bv + l * D_, nullptr, c_, NTOK, D_, D_);
        tcg<64,  ACT_ELU1, false, false>(a_, Ph + md, Pl_ + md, nullptr, nullptr, pq_, NTOK, M_, D_);
        tcg<64,  ACT_ELU1, false, false>(b_, Ph + md, Pl_ + md, nullptr, nullptr, pk_, NTOK, M_, D_);
        kv_kernel<<<dim3(D_ / 64, B_), 256>>>(pk_, c_, kv_);
        pksum_part<<<dim3(16, B_), 64>>>(pk_, pkp_);
        pksum_red<<<B_, 64>>>(pkp_, pks_);
        att_kernel<8><<<dim3(S_ / 8, B_), 256>>>(pq_, kv_, pks_, a_, S_);
        tcg<128, ACT_NONE, true, false>(a_, Woh + dd, Wol_ + dd, bo + l * D_, nullptr, b_, NTOK, D_, D_);
        ln_kernel<<<NTOK, 128>>>(b_, lng + l * D_, lnb + l * D_, a_);
        tcg<128, ACT_GELU, true, false>(a_, W1h + hd, W1l_ + hd, b1 + l * H_, nullptr, ff_, NTOK, H_, D_);
        tcg<128, ACT_NONE, true, true >(ff_, W2h + dh, W2l_ + dh, b2 + l * D_, h_, h_, NTOK, D_, H_);
    }

    { // layer 3: only position 0 survives
        const int l = 3;
        const size_t dd = (size_t)l * D_ * D_, md = (size_t)l * M_ * D_;
        gather0_kernel<<<B_, 128>>>(h_, s0_);
        tcg<128, ACT_NONE, true, false>(h_, Wkh + dd, Wkl_ + dd, bk + l * D_, nullptr, b_, NTOK, D_, D_);
        tcg<128, ACT_NONE, true, false>(h_, Wvh + dd, Wvl_ + dd, bv + l * D_, nullptr, c_, NTOK, D_, D_);
        tcg<64,  ACT_ELU1, false, false>(b_, Ph + md, Pl_ + md, nullptr, nullptr, pk_, NTOK, M_, D_);
        kv_kernel<<<dim3(D_ / 64, B_), 256>>>(pk_, c_, kv_);
        pksum_part<<<dim3(16, B_), 64>>>(pk_, pkp_);
        pksum_red<<<B_, 64>>>(pkp_, pks_);

        gemm128<ACT_NONE, true, false>(s0_, Wq + dd, bq + l * D_, nullptr, s1_, B_, D_, D_);
        gemm64n<ACT_ELU1>(s1_, P + md, s2_, B_, D_);
        att_kernel<1><<<dim3(1, B_), 256>>>(s2_, kv_, pks_, s3_, 1);
        gemm128<ACT_NONE, true, false>(s3_, Wo + dd, bo + l * D_, nullptr, s1_, B_, D_, D_);
        ln_kernel<<<B_, 128>>>(s1_, lng + l * D_, lnb + l * D_, s3_);
        gemm128<ACT_GELU, true, false>(s3_, W1 + (size_t)l * D_ * H_, b1 + l * H_, nullptr, sff_, B_, H_, D_);
        gemm128<ACT_NONE, true, true >(sff_, W2 + (size_t)l * H_ * D_, b2 + l * D_, s0_, s1_, B_, D_, H_);
    }

    cls_kernel<<<B_, 256>>>(s1_, Wc1, bc1, Wc2, bc2, out);
}